// round 10
// baseline (speedup 1.0000x reference)
#include <cuda_runtime.h>
#include <math.h>
#include <stdint.h>

// Problem constants
#define BB    64      // batch
#define TT    1024    // timesteps
#define HH    256     // hidden
#define NCTA  128     // persistent CTAs (each owns 2 hidden units, both layers)
#define NT    128     // threads: tid = u*64 + b

#define NCHUNK       4
#define M_PER_CHUNK  32
#define CHUNK_FLOATS 4096    // per h-array per chunk
#define CHUNK_BYTES  16384

typedef unsigned long long ull;

// Persistent device state (static allocation only)
// h layout: [pair m][batch b][e]  ->  idx = m*128 + b*2 + e,  unit k = 2m+e
// CTA k writes pair m = k, i.e. floats [k*128, (k+1)*128): chunk c of each h
// array is produced exactly by CTAs [32c, 32c+32)  ->  per-chunk barriers.
__device__ __align__(128) float g_h0[2][HH * BB];
__device__ __align__(128) float g_h1[2][HH * BB];
__device__ float    g_hmean[HH * BB];       // [j*64 + b]
__device__ float    g_xT[TT * BB];          // [t*64 + b]
// 4 group counters, one 128B line each: counter c at g_gct[c*32].
// CTA cta arrives at counter (cta >> 5); 32 CTAs per counter per slot.
__device__ __align__(128) unsigned g_gct[4 * 32];

// ---------------------------------------------------------------------------
__global__ void init_kernel(const float* __restrict__ x) {
    int i = blockIdx.x * blockDim.x + threadIdx.x;
    if (i < 4 * 32) g_gct[i] = 0u;
    if (i < TT * BB) {
        int t = i >> 6;
        int b = i & 63;
        g_xT[i] = x[b * TT + t];
    }
    if (i < HH * BB) {
        g_h0[0][i] = 0.f; g_h0[1][i] = 0.f;
        g_h1[0][i] = 0.f; g_h1[1][i] = 0.f;
    }
}

// ---------------------------------------------------------------------------
// helpers
// ---------------------------------------------------------------------------
__device__ __forceinline__ uint32_t smem_u32(const void* p) {
    uint32_t a;
    asm("{ .reg .u64 t; cvta.to.shared.u64 t, %1; cvt.u32.u64 %0, t; }"
        : "=r"(a) : "l"(p));
    return a;
}

__device__ __forceinline__ void fma2(ull& d, ull a, ull b) {
    asm("fma.rn.f32x2 %0, %1, %2, %0;" : "+l"(d) : "l"(a), "l"(b));
}

__device__ __forceinline__ ull pack2(float lo, float hi) {
    ull v; asm("mov.b64 %0, {%1, %2};" : "=l"(v) : "f"(lo), "f"(hi)); return v;
}

__device__ __forceinline__ float hadd2(ull v) {
    float lo, hi; asm("mov.b64 {%0, %1}, %2;" : "=f"(lo), "=f"(hi) : "l"(v));
    return lo + hi;
}

__device__ __forceinline__ void mbar_init(uint32_t a, unsigned cnt) {
    asm volatile("mbarrier.init.shared.b64 [%0], %1;" :: "r"(a), "r"(cnt) : "memory");
}

__device__ __forceinline__ void mbar_expect_tx(uint32_t a, unsigned bytes) {
    asm volatile("mbarrier.arrive.expect_tx.shared.b64 _, [%0], %1;"
                 :: "r"(a), "r"(bytes) : "memory");
}

__device__ __forceinline__ void mbar_wait(uint32_t a, unsigned parity) {
    asm volatile(
        "{\n\t.reg .pred P;\n\t"
        "WL%=:\n\t"
        "mbarrier.try_wait.parity.acquire.cta.shared::cta.b64 P, [%0], %1, 0x989680;\n\t"
        "@P bra.uni WD%=;\n\t"
        "bra.uni WL%=;\n\t"
        "WD%=:\n\t}"
        :: "r"(a), "r"(parity) : "memory");
}

__device__ __forceinline__ void bulk_g2s(uint32_t dst, const void* src,
                                         unsigned bytes, uint32_t mbar) {
    asm volatile(
        "cp.async.bulk.shared::cluster.global.mbarrier::complete_tx::bytes "
        "[%0], [%1], %2, [%3];"
        :: "r"(dst), "l"(src), "r"(bytes), "r"(mbar) : "memory");
}

__device__ __forceinline__ float sigm(float x) {
    return __fdividef(1.f, 1.f + __expf(-x));
}
__device__ __forceinline__ float tanh_f(float x) {
    float e = __expf(-2.f * fabsf(x));
    float t = __fdividef(1.f - e, 1.f + e);
    return copysignf(t, x);
}

// ---------------------------------------------------------------------------
// Persistent fused 2-layer LSTM.
// Slot t: layer0 computes step t (t<TT); layer1 computes step t-1 (t>0).
//
// Per-chunk fine-grained global barrier:
//   - each thread fences its own h stores, then __syncthreads()
//   - tid0 arrives at its GROUP counter (4 counters, 32 CTAs each)
//   - tid0 polls counter c, then immediately issues chunk c's TMA pair:
//     chunk 0 is issued as soon as the first 32 CTAs are done — no global
//     rendezvous; arrivals of groups 1..3 hide under chunk 0..2 compute.
//   - warps 1..3 are gated by the chunk mbarriers (proven R2 control flow).
// ---------------------------------------------------------------------------
__global__ void __launch_bounds__(NT, 1) lstm_persistent(
    const float* __restrict__ Wh0, const float* __restrict__ Wx0,
    const float* __restrict__ b0,
    const float* __restrict__ Wx1, const float* __restrict__ Wh1,
    const float* __restrict__ b1)
{
    extern __shared__ float smem[];
    // layout (floats): sh0[16384] | sh1[16384] | w0[2048] | wx[2048] | w1[2048] | mbars
    float* sh0 = smem;
    float* sh1 = smem + 16384;
    float* w0s = smem + 32768;
    float* wxs = smem + 34816;
    float* w1s = smem + 36864;

    const uint32_t sbase   = smem_u32(smem);
    const uint32_t sh1_u32 = sbase + 65536;
    const uint32_t mbar_u  = sbase + 155648;

    const int tid = threadIdx.x;
    const int b   = tid & 63;
    const int u   = tid >> 6;
    const int j   = blockIdx.x * 2 + u;

    if (tid == 0) {
        #pragma unroll
        for (int c = 0; c < NCHUNK; ++c) mbar_init(mbar_u + c * 8, 1);
    }

    // Preload weight slices as k-pair float2 per gate:
    // w[(m*2+u)*4 + g] = { W[2m][g*256+j], W[2m+1][g*256+j] }
    for (int idx = tid; idx < 256; idx += NT) {
        const int m  = idx >> 1;
        const int uu = idx & 1;
        const int jj = blockIdx.x * 2 + uu;
        float2* d0 = (float2*)w0s + idx * 4;
        float2* dx = (float2*)wxs + idx * 4;
        float2* d1 = (float2*)w1s + idx * 4;
        const float* ra0 = Wh0 + (2 * m) * 1024;
        const float* rb0 = Wh0 + (2 * m + 1) * 1024;
        const float* rax = Wx1 + (2 * m) * 1024;
        const float* rbx = Wx1 + (2 * m + 1) * 1024;
        const float* ra1 = Wh1 + (2 * m) * 1024;
        const float* rb1 = Wh1 + (2 * m + 1) * 1024;
        #pragma unroll
        for (int g = 0; g < 4; ++g) {
            d0[g] = make_float2(ra0[g * 256 + jj], rb0[g * 256 + jj]);
            dx[g] = make_float2(rax[g * 256 + jj], rbx[g * 256 + jj]);
            d1[g] = make_float2(ra1[g * 256 + jj], rb1[g * 256 + jj]);
        }
    }
    const float4 bia0 = make_float4(b0[j], b0[256 + j], b0[512 + j], b0[768 + j]);
    const float4 bia1 = make_float4(b1[j], b1[256 + j], b1[512 + j], b1[768 + j]);
    const float4 wx0  = make_float4(Wx0[j], Wx0[256 + j], Wx0[512 + j], Wx0[768 + j]);

    float c0 = 0.f, c1 = 0.f, hsum = 0.f;
    __syncthreads();   // mbar init + weights visible

    // per-thread pointers for the inner loop
    const ull* ph0 = (const ull*)sh0 + b;             // hv2  at ph0[m*64]
    const ull* ph1 = (const ull*)sh1 + b;             // h1v2 at ph1[m*64]
    const ulonglong2* pw0 = (const ulonglong2*)w0s + u * 2;   // [m*4], [m*4+1]
    const ulonglong2* pwx = (const ulonglong2*)wxs + u * 2;
    const ulonglong2* pw1 = (const ulonglong2*)w1s + u * 2;

    const int houti = (j >> 1) * 128 + b * 2 + (j & 1);

    for (int t = 0; t <= TT; ++t) {
        if (t > 0) {
            __threadfence();      // own h stores -> L2 (parallel across threads)
            __syncthreads();      // whole CTA done with previous slot
        }

        if (tid == 0) {
            if (t > 0) {
                // arrive at own group's counter (fire-and-forget RED)
                atomicAdd(&g_gct[(blockIdx.x >> 5) * 32], 1u);
            }
            asm volatile("fence.proxy.async;" ::: "memory");
            const float* s0 = g_h0[(t + 1) & 1];
            const float* s1 = g_h1[t & 1];
            const unsigned target = (unsigned)t * 32u;   // 32 CTAs per counter
            #pragma unroll
            for (int c = 0; c < NCHUNK; ++c) {
                if (t > 0) {
                    // wait only for the 32 producers of chunk c
                    volatile unsigned* vc = (volatile unsigned*)&g_gct[c * 32];
                    while (*vc < target) { }
                }
                const uint32_t mb = mbar_u + c * 8;
                mbar_expect_tx(mb, 2 * CHUNK_BYTES);
                bulk_g2s(sbase   + c * CHUNK_BYTES, s0 + c * CHUNK_FLOATS, CHUNK_BYTES, mb);
                bulk_g2s(sh1_u32 + c * CHUNK_BYTES, s1 + c * CHUNK_FLOATS, CHUNK_BYTES, mb);
            }
        }
        // warps 1..3 (and warp 0 after issue) are gated by the chunk mbars.

        // init gate accumulators (lane-lo gets bias + x-contribution)
        const float xv = (t < TT) ? g_xT[t * BB + b] : 0.f;
        ull a0i = pack2(fmaf(xv, wx0.x, bia0.x), 0.f);
        ull a0f = pack2(fmaf(xv, wx0.y, bia0.y), 0.f);
        ull a0g = pack2(fmaf(xv, wx0.z, bia0.z), 0.f);
        ull a0o = pack2(fmaf(xv, wx0.w, bia0.w), 0.f);
        ull a1i = pack2(bia1.x, 0.f);
        ull a1f = pack2(bia1.y, 0.f);
        ull a1g = pack2(bia1.z, 0.f);
        ull a1o = pack2(bia1.w, 0.f);

        const unsigned par = (unsigned)(t & 1);
        #pragma unroll
        for (int c = 0; c < NCHUNK; ++c) {
            mbar_wait(mbar_u + c * 8, par);
            const int mbase = c * M_PER_CHUNK;
            #pragma unroll 8
            for (int mm = 0; mm < M_PER_CHUNK; ++mm) {
                const int m = mbase + mm;
                const ull hv2  = ph0[m * 64];
                const ull h1v2 = ph1[m * 64];
                const ulonglong2 w0a = pw0[m * 4];
                const ulonglong2 w0b = pw0[m * 4 + 1];
                fma2(a0i, hv2, w0a.x); fma2(a0f, hv2, w0a.y);
                fma2(a0g, hv2, w0b.x); fma2(a0o, hv2, w0b.y);
                const ulonglong2 wxa = pwx[m * 4];
                const ulonglong2 wxb = pwx[m * 4 + 1];
                fma2(a1i, hv2, wxa.x); fma2(a1f, hv2, wxa.y);
                fma2(a1g, hv2, wxb.x); fma2(a1o, hv2, wxb.y);
                const ulonglong2 w1a = pw1[m * 4];
                const ulonglong2 w1b = pw1[m * 4 + 1];
                fma2(a1i, h1v2, w1a.x); fma2(a1f, h1v2, w1a.y);
                fma2(a1g, h1v2, w1b.x); fma2(a1o, h1v2, w1b.y);
            }
        }

        if (t < TT) {   // layer0 step t
            const float ig = sigm(hadd2(a0i));
            const float fg = sigm(hadd2(a0f));
            const float gg = tanh_f(hadd2(a0g));
            const float og = sigm(hadd2(a0o));
            c0 = fmaf(fg, c0, ig * gg);
            const float h0n = og * tanh_f(c0);
            __stcg(&g_h0[t & 1][houti], h0n);
        }
        if (t > 0) {    // layer1 step t-1
            const float ig = sigm(hadd2(a1i));
            const float fg = sigm(hadd2(a1f));
            const float gg = tanh_f(hadd2(a1g));
            const float og = sigm(hadd2(a1o));
            c1 = fmaf(fg, c1, ig * gg);
            const float h1n = og * tanh_f(c1);
            hsum += h1n;
            if (t < TT) __stcg(&g_h1[(t + 1) & 1][houti], h1n);
        }
    }

    g_hmean[j * 64 + b] = hsum * (1.f / 1024.f);
}

// ---------------------------------------------------------------------------
// Head: theta projection, concat, 3x (dense + ELU), final dense. Runs once.
// ---------------------------------------------------------------------------
__global__ void final_kernel(
    const float* __restrict__ theta,
    const float* __restrict__ pW, const float* __restrict__ pb,
    const float* __restrict__ l0W, const float* __restrict__ l0b,
    const float* __restrict__ l1W, const float* __restrict__ l1b,
    const float* __restrict__ l2W, const float* __restrict__ l2b,
    const float* __restrict__ oW,  const float* __restrict__ ob,
    float* __restrict__ out)
{
    __shared__ float hin[512];
    __shared__ float act0[256];
    __shared__ float act1[256];
    __shared__ float act2[128];
    const int bb = blockIdx.x;
    const int tj = threadIdx.x;

    hin[tj] = g_hmean[tj * 64 + bb];
    {
        float s = pb[tj];
        #pragma unroll
        for (int d = 0; d < 5; ++d) s = fmaf(theta[bb * 5 + d], pW[d * 256 + tj], s);
        hin[256 + tj] = s;
    }
    __syncthreads();
    {
        float acc = l0b[tj];
        for (int k = 0; k < 512; ++k) acc = fmaf(hin[k], l0W[k * 256 + tj], acc);
        act0[tj] = acc > 0.f ? acc : expm1f(acc);
    }
    __syncthreads();
    {
        float acc = l1b[tj];
        for (int k = 0; k < 256; ++k) acc = fmaf(act0[k], l1W[k * 256 + tj], acc);
        act1[tj] = acc > 0.f ? acc : expm1f(acc);
    }
    __syncthreads();
    if (tj < 128) {
        float acc = l2b[tj];
        for (int k = 0; k < 256; ++k) acc = fmaf(act1[k], l2W[k * 128 + tj], acc);
        act2[tj] = acc > 0.f ? acc : expm1f(acc);
    }
    __syncthreads();
    if (tj == 0) {
        float s = ob[0];
        for (int k = 0; k < 128; ++k) s = fmaf(act2[k], oW[k], s);
        out[bb] = s;
    }
}

// ---------------------------------------------------------------------------
extern "C" void kernel_launch(void* const* d_in, const int* in_sizes, int n_in,
                              void* d_out, int out_size) {
    const float* x     = (const float*)d_in[0];
    const float* theta = (const float*)d_in[1];
    const float* Wx0   = (const float*)d_in[2];
    const float* Wh0   = (const float*)d_in[3];
    const float* b0    = (const float*)d_in[4];
    const float* Wx1   = (const float*)d_in[5];
    const float* Wh1   = (const float*)d_in[6];
    const float* b1    = (const float*)d_in[7];
    const float* pW    = (const float*)d_in[8];
    const float* pb    = (const float*)d_in[9];
    const float* l0W   = (const float*)d_in[10];
    const float* l0b   = (const float*)d_in[11];
    const float* l1W   = (const float*)d_in[12];
    const float* l1b   = (const float*)d_in[13];
    const float* l2W   = (const float*)d_in[14];
    const float* l2b   = (const float*)d_in[15];
    const float* oW    = (const float*)d_in[16];
    const float* ob    = (const float*)d_in[17];

    // 64K + 64K + 3*8K floats + mbars = 155648 + 64 bytes
    const int smem_bytes = 155712;
    cudaFuncSetAttribute(lstm_persistent,
                         cudaFuncAttributeMaxDynamicSharedMemorySize, smem_bytes);

    init_kernel<<<(TT * BB + 255) / 256, 256>>>(x);
    lstm_persistent<<<NCTA, NT, smem_bytes>>>(Wh0, Wx0, b0, Wx1, Wh1, b1);
    final_kernel<<<BB, 256>>>(theta, pW, pb, l0W, l0b, l1W, l1b,
                              l2W, l2b, oW, ob, (float*)d_out);
}

// round 11
// speedup vs baseline: 1.5181x; 1.5181x over previous
#include <cuda_runtime.h>
#include <math.h>
#include <stdint.h>

// Problem constants
#define BB    64      // batch
#define TT    1024    // timesteps
#define HH    256     // hidden
#define NCTA  128     // persistent CTAs (each owns 2 hidden units, both layers)
#define NT    128     // threads: tid = u*64 + b

typedef unsigned long long ull;

// Persistent device state (static allocation only)
// h layout: [pair m][batch b][e]  ->  idx = m*128 + b*2 + e,  unit k = 2m+e
__device__ __align__(128) float g_h0[2][HH * BB];
__device__ __align__(128) float g_h1[2][HH * BB];
__device__ float    g_hmean[HH * BB];       // [j*64 + b]
__device__ float    g_xT[TT * BB];          // [t*64 + b]
__device__ unsigned g_ct;                   // single global barrier counter

// ---------------------------------------------------------------------------
__global__ void init_kernel(const float* __restrict__ x) {
    int i = blockIdx.x * blockDim.x + threadIdx.x;
    if (i == 0) g_ct = 0u;
    if (i < TT * BB) {
        int t = i >> 6;
        int b = i & 63;
        g_xT[i] = x[b * TT + t];
    }
    if (i < HH * BB) {
        g_h0[0][i] = 0.f; g_h0[1][i] = 0.f;
        g_h1[0][i] = 0.f; g_h1[1][i] = 0.f;
    }
}

// ---------------------------------------------------------------------------
// helpers
// ---------------------------------------------------------------------------
__device__ __forceinline__ void fma2(ull& d, ull a, ull b) {
    asm("fma.rn.f32x2 %0, %1, %2, %0;" : "+l"(d) : "l"(a), "l"(b));
}

__device__ __forceinline__ ull pack2(float lo, float hi) {
    ull v; asm("mov.b64 %0, {%1, %2};" : "=l"(v) : "f"(lo), "f"(hi)); return v;
}

__device__ __forceinline__ float hadd2(ull v) {
    float lo, hi; asm("mov.b64 {%0, %1}, %2;" : "=f"(lo), "=f"(hi) : "l"(v));
    return lo + hi;
}

__device__ __forceinline__ float sigm(float x) {
    return __fdividef(1.f, 1.f + __expf(-x));
}
__device__ __forceinline__ float tanh_f(float x) {
    float e = __expf(-2.f * fabsf(x));
    float t = __fdividef(1.f - e, 1.f + e);
    return copysignf(t, x);
}

// ---------------------------------------------------------------------------
// Persistent fused 2-layer LSTM — direct-LDG variant (no TMA, no mbarriers).
// Slot t: layer0 computes step t (t<TT); layer1 computes step t-1 (t>0).
//
// Barrier (proven R1/R2 shape): per-thread __threadfence, __syncthreads,
// tid0 atomicAdd + volatile spin on ONE counter, __syncthreads.
//
// h broadcast: each thread reads its (m, b) pairs straight from L2 with
// __ldcg inside the FMA loop, software-pipelined with 3 register buffers
// (blocks of 8 m, prefetch distance 2 ≈ 384 cyc of latency cover).
// ---------------------------------------------------------------------------
__global__ void __launch_bounds__(NT, 1) lstm_persistent(
    const float* __restrict__ Wh0, const float* __restrict__ Wx0,
    const float* __restrict__ b0,
    const float* __restrict__ Wx1, const float* __restrict__ Wh1,
    const float* __restrict__ b1)
{
    __shared__ float w0s[2048];   // Wh0 slice: k-pair float2 per gate
    __shared__ float wxs[2048];   // Wx1 slice
    __shared__ float w1s[2048];   // Wh1 slice

    const int tid = threadIdx.x;
    const int b   = tid & 63;
    const int u   = tid >> 6;
    const int j   = blockIdx.x * 2 + u;

    // Preload weight slices as k-pair float2 per gate:
    // w[(m*2+u)*4 + g] = { W[2m][g*256+j], W[2m+1][g*256+j] }
    for (int idx = tid; idx < 256; idx += NT) {
        const int m  = idx >> 1;
        const int uu = idx & 1;
        const int jj = blockIdx.x * 2 + uu;
        float2* d0 = (float2*)w0s + idx * 4;
        float2* dx = (float2*)wxs + idx * 4;
        float2* d1 = (float2*)w1s + idx * 4;
        const float* ra0 = Wh0 + (2 * m) * 1024;
        const float* rb0 = Wh0 + (2 * m + 1) * 1024;
        const float* rax = Wx1 + (2 * m) * 1024;
        const float* rbx = Wx1 + (2 * m + 1) * 1024;
        const float* ra1 = Wh1 + (2 * m) * 1024;
        const float* rb1 = Wh1 + (2 * m + 1) * 1024;
        #pragma unroll
        for (int g = 0; g < 4; ++g) {
            d0[g] = make_float2(ra0[g * 256 + jj], rb0[g * 256 + jj]);
            dx[g] = make_float2(rax[g * 256 + jj], rbx[g * 256 + jj]);
            d1[g] = make_float2(ra1[g * 256 + jj], rb1[g * 256 + jj]);
        }
    }
    const float4 bia0 = make_float4(b0[j], b0[256 + j], b0[512 + j], b0[768 + j]);
    const float4 bia1 = make_float4(b1[j], b1[256 + j], b1[512 + j], b1[768 + j]);
    const float4 wx0  = make_float4(Wx0[j], Wx0[256 + j], Wx0[512 + j], Wx0[768 + j]);

    float c0 = 0.f, c1 = 0.f, hsum = 0.f;
    __syncthreads();   // weights visible

    const ulonglong2* pw0 = (const ulonglong2*)w0s + u * 2;   // [m*4], [m*4+1]
    const ulonglong2* pwx = (const ulonglong2*)wxs + u * 2;
    const ulonglong2* pw1 = (const ulonglong2*)w1s + u * 2;

    const int houti = (j >> 1) * 128 + b * 2 + (j & 1);

    for (int t = 0; t <= TT; ++t) {
        if (t > 0) {
            __threadfence();      // own h stores -> L2 (parallel across threads)
            __syncthreads();      // whole CTA done with previous slot
            if (tid == 0) {
                atomicAdd(&g_ct, 1u);
                const unsigned target = (unsigned)t * NCTA;
                while (*((volatile unsigned*)&g_ct) < target) { }
            }
            __syncthreads();      // release whole CTA
        }

        // init gate accumulators (lane-lo gets bias + x-contribution)
        const float xv = (t < TT) ? g_xT[t * BB + b] : 0.f;
        ull a0i = pack2(fmaf(xv, wx0.x, bia0.x), 0.f);
        ull a0f = pack2(fmaf(xv, wx0.y, bia0.y), 0.f);
        ull a0g = pack2(fmaf(xv, wx0.z, bia0.z), 0.f);
        ull a0o = pack2(fmaf(xv, wx0.w, bia0.w), 0.f);
        ull a1i = pack2(bia1.x, 0.f);
        ull a1f = pack2(bia1.y, 0.f);
        ull a1g = pack2(bia1.z, 0.f);
        ull a1o = pack2(bia1.w, 0.f);

        // h pair (m, b) of layer L at pL[m*64]
        const ull* p0 = (const ull*)g_h0[(t + 1) & 1] + b;
        const ull* p1 = (const ull*)g_h1[t & 1] + b;

        // 3-buffer software pipeline: blocks of 8 m, prefetch distance 2.
        ull bh0[3][8], bh1[3][8];
        #pragma unroll
        for (int i = 0; i < 8; ++i) {
            bh0[0][i] = __ldcg(p0 + i * 64);
            bh1[0][i] = __ldcg(p1 + i * 64);
        }
        #pragma unroll
        for (int i = 0; i < 8; ++i) {
            bh0[1][i] = __ldcg(p0 + (8 + i) * 64);
            bh1[1][i] = __ldcg(p1 + (8 + i) * 64);
        }

        #pragma unroll
        for (int blk = 0; blk < 16; ++blk) {
            const int ld = blk + 2;
            if (ld < 16) {
                #pragma unroll
                for (int i = 0; i < 8; ++i) {
                    bh0[ld % 3][i] = __ldcg(p0 + (ld * 8 + i) * 64);
                    bh1[ld % 3][i] = __ldcg(p1 + (ld * 8 + i) * 64);
                }
            }
            #pragma unroll
            for (int i = 0; i < 8; ++i) {
                const int m = blk * 8 + i;
                const ull hv2  = bh0[blk % 3][i];
                const ull h1v2 = bh1[blk % 3][i];
                const ulonglong2 w0a = pw0[m * 4];
                const ulonglong2 w0b = pw0[m * 4 + 1];
                fma2(a0i, hv2, w0a.x); fma2(a0f, hv2, w0a.y);
                fma2(a0g, hv2, w0b.x); fma2(a0o, hv2, w0b.y);
                const ulonglong2 wxa = pwx[m * 4];
                const ulonglong2 wxb = pwx[m * 4 + 1];
                fma2(a1i, hv2, wxa.x); fma2(a1f, hv2, wxa.y);
                fma2(a1g, hv2, wxb.x); fma2(a1o, hv2, wxb.y);
                const ulonglong2 w1a = pw1[m * 4];
                const ulonglong2 w1b = pw1[m * 4 + 1];
                fma2(a1i, h1v2, w1a.x); fma2(a1f, h1v2, w1a.y);
                fma2(a1g, h1v2, w1b.x); fma2(a1o, h1v2, w1b.y);
            }
        }

        if (t < TT) {   // layer0 step t
            const float ig = sigm(hadd2(a0i));
            const float fg = sigm(hadd2(a0f));
            const float gg = tanh_f(hadd2(a0g));
            const float og = sigm(hadd2(a0o));
            c0 = fmaf(fg, c0, ig * gg);
            const float h0n = og * tanh_f(c0);
            __stcg(&g_h0[t & 1][houti], h0n);
        }
        if (t > 0) {    // layer1 step t-1
            const float ig = sigm(hadd2(a1i));
            const float fg = sigm(hadd2(a1f));
            const float gg = tanh_f(hadd2(a1g));
            const float og = sigm(hadd2(a1o));
            c1 = fmaf(fg, c1, ig * gg);
            const float h1n = og * tanh_f(c1);
            hsum += h1n;
            if (t < TT) __stcg(&g_h1[(t + 1) & 1][houti], h1n);
        }
    }

    g_hmean[j * 64 + b] = hsum * (1.f / 1024.f);
}

// ---------------------------------------------------------------------------
// Head: theta projection, concat, 3x (dense + ELU), final dense. Runs once.
// ---------------------------------------------------------------------------
__global__ void final_kernel(
    const float* __restrict__ theta,
    const float* __restrict__ pW, const float* __restrict__ pb,
    const float* __restrict__ l0W, const float* __restrict__ l0b,
    const float* __restrict__ l1W, const float* __restrict__ l1b,
    const float* __restrict__ l2W, const float* __restrict__ l2b,
    const float* __restrict__ oW,  const float* __restrict__ ob,
    float* __restrict__ out)
{
    __shared__ float hin[512];
    __shared__ float act0[256];
    __shared__ float act1[256];
    __shared__ float act2[128];
    const int bb = blockIdx.x;
    const int tj = threadIdx.x;

    hin[tj] = g_hmean[tj * 64 + bb];
    {
        float s = pb[tj];
        #pragma unroll
        for (int d = 0; d < 5; ++d) s = fmaf(theta[bb * 5 + d], pW[d * 256 + tj], s);
        hin[256 + tj] = s;
    }
    __syncthreads();
    {
        float acc = l0b[tj];
        for (int k = 0; k < 512; ++k) acc = fmaf(hin[k], l0W[k * 256 + tj], acc);
        act0[tj] = acc > 0.f ? acc : expm1f(acc);
    }
    __syncthreads();
    {
        float acc = l1b[tj];
        for (int k = 0; k < 256; ++k) acc = fmaf(act0[k], l1W[k * 256 + tj], acc);
        act1[tj] = acc > 0.f ? acc : expm1f(acc);
    }
    __syncthreads();
    if (tj < 128) {
        float acc = l2b[tj];
        for (int k = 0; k < 256; ++k) acc = fmaf(act1[k], l2W[k * 128 + tj], acc);
        act2[tj] = acc > 0.f ? acc : expm1f(acc);
    }
    __syncthreads();
    if (tj == 0) {
        float s = ob[0];
        for (int k = 0; k < 128; ++k) s = fmaf(act2[k], oW[k], s);
        out[bb] = s;
    }
}

// ---------------------------------------------------------------------------
extern "C" void kernel_launch(void* const* d_in, const int* in_sizes, int n_in,
                              void* d_out, int out_size) {
    const float* x     = (const float*)d_in[0];
    const float* theta = (const float*)d_in[1];
    const float* Wx0   = (const float*)d_in[2];
    const float* Wh0   = (const float*)d_in[3];
    const float* b0    = (const float*)d_in[4];
    const float* Wx1   = (const float*)d_in[5];
    const float* Wh1   = (const float*)d_in[6];
    const float* b1    = (const float*)d_in[7];
    const float* pW    = (const float*)d_in[8];
    const float* pb    = (const float*)d_in[9];
    const float* l0W   = (const float*)d_in[10];
    const float* l0b   = (const float*)d_in[11];
    const float* l1W   = (const float*)d_in[12];
    const float* l1b   = (const float*)d_in[13];
    const float* l2W   = (const float*)d_in[14];
    const float* l2b   = (const float*)d_in[15];
    const float* oW    = (const float*)d_in[16];
    const float* ob    = (const float*)d_in[17];

    init_kernel<<<(TT * BB + 255) / 256, 256>>>(x);
    lstm_persistent<<<NCTA, NT>>>(Wh0, Wx0, b0, Wx1, Wh1, b1);
    final_kernel<<<BB, 256>>>(theta, pW, pb, l0W, l0b, l1W, l1b,
                              l2W, l2b, oW, ob, (float*)d_out);
}

// round 12
// speedup vs baseline: 1.6968x; 1.1177x over previous
#include <cuda_runtime.h>
#include <cuda_fp16.h>
#include <math.h>
#include <stdint.h>

// Problem constants
#define BB    64      // batch
#define TT    1024    // timesteps
#define HH    256     // hidden
#define NCTA  128     // persistent CTAs (each owns 2 hidden units, both layers)
#define NT    128     // threads: tid = u*64 + b

#define NCHUNK       4
#define M_PER_CHUNK  32
#define CHUNK_HALFS  4096    // per h-array per chunk (fp16)
#define CHUNK_BYTES  8192

typedef unsigned long long ull;

// Persistent device state (static allocation only)
// h stored as fp16: [pair m][batch b][e] -> half idx = m*128 + b*2 + e
__device__ __align__(128) unsigned short g_h0[2][HH * BB];
__device__ __align__(128) unsigned short g_h1[2][HH * BB];
__device__ float    g_hmean[HH * BB];       // [j*64 + b]
__device__ float    g_xT[TT * BB];          // [t*64 + b]
__device__ unsigned g_ct;                   // global barrier counter (monotonic)

// ---------------------------------------------------------------------------
__global__ void init_kernel(const float* __restrict__ x) {
    int i = blockIdx.x * blockDim.x + threadIdx.x;
    if (i == 0) g_ct = 0u;
    if (i < TT * BB) {
        int t = i >> 6;
        int b = i & 63;
        g_xT[i] = x[b * TT + t];
    }
    if (i < HH * BB) {
        g_h0[0][i] = 0; g_h0[1][i] = 0;   // 0x0000 == +0.0 in fp16
        g_h1[0][i] = 0; g_h1[1][i] = 0;
    }
}

// ---------------------------------------------------------------------------
// helpers
// ---------------------------------------------------------------------------
__device__ __forceinline__ uint32_t smem_u32(const void* p) {
    uint32_t a;
    asm("{ .reg .u64 t; cvta.to.shared.u64 t, %1; cvt.u32.u64 %0, t; }"
        : "=r"(a) : "l"(p));
    return a;
}

__device__ __forceinline__ void fma2(ull& d, ull a, ull b) {
    asm("fma.rn.f32x2 %0, %1, %2, %0;" : "+l"(d) : "l"(a), "l"(b));
}

__device__ __forceinline__ ull pack2(float lo, float hi) {
    ull v; asm("mov.b64 %0, {%1, %2};" : "=l"(v) : "f"(lo), "f"(hi)); return v;
}

__device__ __forceinline__ float hadd2(ull v) {
    float lo, hi; asm("mov.b64 {%0, %1}, %2;" : "=f"(lo), "=f"(hi) : "l"(v));
    return lo + hi;
}

// packed half2 (as uint) -> packed f32x2 (as ull)
__device__ __forceinline__ ull h2_to_f32x2(uint32_t h2) {
    ull v;
    asm("{ .reg .b16 l, h; .reg .f32 fl, fh;\n\t"
        "mov.b32 {l, h}, %1;\n\t"
        "cvt.f32.f16 fl, l;\n\t"
        "cvt.f32.f16 fh, h;\n\t"
        "mov.b64 %0, {fl, fh}; }"
        : "=l"(v) : "r"(h2));
    return v;
}

__device__ __forceinline__ void st_h16(unsigned short* p, float f) {
    unsigned short hr = __half_as_ushort(__float2half_rn(f));
    asm volatile("st.global.cg.u16 [%0], %1;" :: "l"(p), "h"(hr) : "memory");
}

__device__ __forceinline__ void mbar_init(uint32_t a, unsigned cnt) {
    asm volatile("mbarrier.init.shared.b64 [%0], %1;" :: "r"(a), "r"(cnt) : "memory");
}

__device__ __forceinline__ void mbar_expect_tx(uint32_t a, unsigned bytes) {
    asm volatile("mbarrier.arrive.expect_tx.shared.b64 _, [%0], %1;"
                 :: "r"(a), "r"(bytes) : "memory");
}

__device__ __forceinline__ void mbar_wait(uint32_t a, unsigned parity) {
    asm volatile(
        "{\n\t.reg .pred P;\n\t"
        "WL%=:\n\t"
        "mbarrier.try_wait.parity.acquire.cta.shared::cta.b64 P, [%0], %1, 0x989680;\n\t"
        "@P bra.uni WD%=;\n\t"
        "bra.uni WL%=;\n\t"
        "WD%=:\n\t}"
        :: "r"(a), "r"(parity) : "memory");
}

__device__ __forceinline__ void bulk_g2s(uint32_t dst, const void* src,
                                         unsigned bytes, uint32_t mbar) {
    asm volatile(
        "cp.async.bulk.shared::cluster.global.mbarrier::complete_tx::bytes "
        "[%0], [%1], %2, [%3];"
        :: "r"(dst), "l"(src), "r"(bytes), "r"(mbar) : "memory");
}

__device__ __forceinline__ float sigm(float x) {
    return __fdividef(1.f, 1.f + __expf(-x));
}
__device__ __forceinline__ float tanh_f(float x) {
    float e = __expf(-2.f * fabsf(x));
    float t = __fdividef(1.f - e, 1.f + e);
    return copysignf(t, x);
}

// ---------------------------------------------------------------------------
// Persistent fused 2-layer LSTM — fp16 h exchange (halves the L2 broadcast).
// Slot t: layer0 computes step t (t<TT); layer1 computes step t-1 (t>0).
// Control flow identical to the proven R2 kernel: per-thread fence + sync,
// tid0 single-counter atomic + volatile spin, tid0 issues chunked TMA,
// warps 1..3 gated by chunk mbarriers.
// ---------------------------------------------------------------------------
__global__ void __launch_bounds__(NT, 1) lstm_persistent(
    const float* __restrict__ Wh0, const float* __restrict__ Wx0,
    const float* __restrict__ b0,
    const float* __restrict__ Wx1, const float* __restrict__ Wh1,
    const float* __restrict__ b1)
{
    extern __shared__ char smem[];
    // bytes: sh0[32768] | sh1[32768] | w0[8192] | wx[8192] | w1[8192] | mbars
    float* w0s = (float*)(smem + 65536);
    float* wxs = (float*)(smem + 65536 + 8192);
    float* w1s = (float*)(smem + 65536 + 16384);

    const uint32_t sbase   = smem_u32(smem);
    const uint32_t sh1_u32 = sbase + 32768;
    const uint32_t mbar_u  = sbase + 90112;

    const int tid = threadIdx.x;
    const int b   = tid & 63;
    const int u   = tid >> 6;
    const int j   = blockIdx.x * 2 + u;

    if (tid == 0) {
        #pragma unroll
        for (int c = 0; c < NCHUNK; ++c) mbar_init(mbar_u + c * 8, 1);
    }

    // Preload weight slices as k-pair float2 per gate:
    // w[(m*2+u)*4 + g] = { W[2m][g*256+j], W[2m+1][g*256+j] }
    for (int idx = tid; idx < 256; idx += NT) {
        const int m  = idx >> 1;
        const int uu = idx & 1;
        const int jj = blockIdx.x * 2 + uu;
        float2* d0 = (float2*)w0s + idx * 4;
        float2* dx = (float2*)wxs + idx * 4;
        float2* d1 = (float2*)w1s + idx * 4;
        const float* ra0 = Wh0 + (2 * m) * 1024;
        const float* rb0 = Wh0 + (2 * m + 1) * 1024;
        const float* rax = Wx1 + (2 * m) * 1024;
        const float* rbx = Wx1 + (2 * m + 1) * 1024;
        const float* ra1 = Wh1 + (2 * m) * 1024;
        const float* rb1 = Wh1 + (2 * m + 1) * 1024;
        #pragma unroll
        for (int g = 0; g < 4; ++g) {
            d0[g] = make_float2(ra0[g * 256 + jj], rb0[g * 256 + jj]);
            dx[g] = make_float2(rax[g * 256 + jj], rbx[g * 256 + jj]);
            d1[g] = make_float2(ra1[g * 256 + jj], rb1[g * 256 + jj]);
        }
    }
    const float4 bia0 = make_float4(b0[j], b0[256 + j], b0[512 + j], b0[768 + j]);
    const float4 bia1 = make_float4(b1[j], b1[256 + j], b1[512 + j], b1[768 + j]);
    const float4 wx0  = make_float4(Wx0[j], Wx0[256 + j], Wx0[512 + j], Wx0[768 + j]);

    float c0 = 0.f, c1 = 0.f, hsum = 0.f;
    __syncthreads();   // mbar init + weights visible

    // per-thread pointers: half2 pair (m,b) at pX[m*64] (uint view)
    const uint32_t* ph0 = (const uint32_t*)smem + b;
    const uint32_t* ph1 = (const uint32_t*)(smem + 32768) + b;
    const ulonglong2* pw0 = (const ulonglong2*)w0s + u * 2;   // [m*4], [m*4+1]
    const ulonglong2* pwx = (const ulonglong2*)wxs + u * 2;
    const ulonglong2* pw1 = (const ulonglong2*)w1s + u * 2;

    const int houti = (j >> 1) * 128 + b * 2 + (j & 1);

    for (int t = 0; t <= TT; ++t) {
        if (t > 0) {
            __threadfence();      // own h stores -> L2 (parallel across threads)
            __syncthreads();      // whole CTA done with previous slot
            if (tid == 0) {
                atomicAdd(&g_ct, 1u);
                const unsigned target = (unsigned)t * NCTA;
                while (*((volatile unsigned*)&g_ct) < target) { }
            }
            // NOTE: no __syncthreads here — other threads run ahead to the
            // mbar waits, which gate on this slot's TMA completions.
        }

        if (tid == 0) {
            asm volatile("fence.proxy.async;" ::: "memory");
            const unsigned short* s0 = g_h0[(t + 1) & 1];
            const unsigned short* s1 = g_h1[t & 1];
            #pragma unroll
            for (int c = 0; c < NCHUNK; ++c) {
                const uint32_t mb = mbar_u + c * 8;
                mbar_expect_tx(mb, 2 * CHUNK_BYTES);
                bulk_g2s(sbase   + c * CHUNK_BYTES, s0 + c * CHUNK_HALFS, CHUNK_BYTES, mb);
                bulk_g2s(sh1_u32 + c * CHUNK_BYTES, s1 + c * CHUNK_HALFS, CHUNK_BYTES, mb);
            }
        }

        // init gate accumulators (lane-lo gets bias + x-contribution)
        const float xv = (t < TT) ? g_xT[t * BB + b] : 0.f;
        ull a0i = pack2(fmaf(xv, wx0.x, bia0.x), 0.f);
        ull a0f = pack2(fmaf(xv, wx0.y, bia0.y), 0.f);
        ull a0g = pack2(fmaf(xv, wx0.z, bia0.z), 0.f);
        ull a0o = pack2(fmaf(xv, wx0.w, bia0.w), 0.f);
        ull a1i = pack2(bia1.x, 0.f);
        ull a1f = pack2(bia1.y, 0.f);
        ull a1g = pack2(bia1.z, 0.f);
        ull a1o = pack2(bia1.w, 0.f);

        const unsigned par = (unsigned)(t & 1);
        #pragma unroll
        for (int c = 0; c < NCHUNK; ++c) {
            mbar_wait(mbar_u + c * 8, par);
            const int mbase = c * M_PER_CHUNK;
            #pragma unroll 8
            for (int mm = 0; mm < M_PER_CHUNK; ++mm) {
                const int m = mbase + mm;
                const ull hv2  = h2_to_f32x2(ph0[m * 64]);
                const ull h1v2 = h2_to_f32x2(ph1[m * 64]);
                const ulonglong2 w0a = pw0[m * 4];
                const ulonglong2 w0b = pw0[m * 4 + 1];
                fma2(a0i, hv2, w0a.x); fma2(a0f, hv2, w0a.y);
                fma2(a0g, hv2, w0b.x); fma2(a0o, hv2, w0b.y);
                const ulonglong2 wxa = pwx[m * 4];
                const ulonglong2 wxb = pwx[m * 4 + 1];
                fma2(a1i, hv2, wxa.x); fma2(a1f, hv2, wxa.y);
                fma2(a1g, hv2, wxb.x); fma2(a1o, hv2, wxb.y);
                const ulonglong2 w1a = pw1[m * 4];
                const ulonglong2 w1b = pw1[m * 4 + 1];
                fma2(a1i, h1v2, w1a.x); fma2(a1f, h1v2, w1a.y);
                fma2(a1g, h1v2, w1b.x); fma2(a1o, h1v2, w1b.y);
            }
        }

        if (t < TT) {   // layer0 step t
            const float ig = sigm(hadd2(a0i));
            const float fg = sigm(hadd2(a0f));
            const float gg = tanh_f(hadd2(a0g));
            const float og = sigm(hadd2(a0o));
            c0 = fmaf(fg, c0, ig * gg);
            const float h0n = og * tanh_f(c0);
            st_h16(&g_h0[t & 1][houti], h0n);
        }
        if (t > 0) {    // layer1 step t-1
            const float ig = sigm(hadd2(a1i));
            const float fg = sigm(hadd2(a1f));
            const float gg = tanh_f(hadd2(a1g));
            const float og = sigm(hadd2(a1o));
            c1 = fmaf(fg, c1, ig * gg);
            const float h1n = og * tanh_f(c1);
            hsum += h1n;
            if (t < TT) st_h16(&g_h1[(t + 1) & 1][houti], h1n);
        }
    }

    g_hmean[j * 64 + b] = hsum * (1.f / 1024.f);
}

// ---------------------------------------------------------------------------
// Head: theta projection, concat, 3x (dense + ELU), final dense. Runs once.
// ---------------------------------------------------------------------------
__global__ void final_kernel(
    const float* __restrict__ theta,
    const float* __restrict__ pW, const float* __restrict__ pb,
    const float* __restrict__ l0W, const float* __restrict__ l0b,
    const float* __restrict__ l1W, const float* __restrict__ l1b,
    const float* __restrict__ l2W, const float* __restrict__ l2b,
    const float* __restrict__ oW,  const float* __restrict__ ob,
    float* __restrict__ out)
{
    __shared__ float hin[512];
    __shared__ float act0[256];
    __shared__ float act1[256];
    __shared__ float act2[128];
    const int bb = blockIdx.x;
    const int tj = threadIdx.x;

    hin[tj] = g_hmean[tj * 64 + bb];
    {
        float s = pb[tj];
        #pragma unroll
        for (int d = 0; d < 5; ++d) s = fmaf(theta[bb * 5 + d], pW[d * 256 + tj], s);
        hin[256 + tj] = s;
    }
    __syncthreads();
    {
        float acc = l0b[tj];
        for (int k = 0; k < 512; ++k) acc = fmaf(hin[k], l0W[k * 256 + tj], acc);
        act0[tj] = acc > 0.f ? acc : expm1f(acc);
    }
    __syncthreads();
    {
        float acc = l1b[tj];
        for (int k = 0; k < 256; ++k) acc = fmaf(act0[k], l1W[k * 256 + tj], acc);
        act1[tj] = acc > 0.f ? acc : expm1f(acc);
    }
    __syncthreads();
    if (tj < 128) {
        float acc = l2b[tj];
        for (int k = 0; k < 256; ++k) acc = fmaf(act1[k], l2W[k * 128 + tj], acc);
        act2[tj] = acc > 0.f ? acc : expm1f(acc);
    }
    __syncthreads();
    if (tj == 0) {
        float s = ob[0];
        for (int k = 0; k < 128; ++k) s = fmaf(act2[k], oW[k], s);
        out[bb] = s;
    }
}

// ---------------------------------------------------------------------------
extern "C" void kernel_launch(void* const* d_in, const int* in_sizes, int n_in,
                              void* d_out, int out_size) {
    const float* x     = (const float*)d_in[0];
    const float* theta = (const float*)d_in[1];
    const float* Wx0   = (const float*)d_in[2];
    const float* Wh0   = (const float*)d_in[3];
    const float* b0    = (const float*)d_in[4];
    const float* Wx1   = (const float*)d_in[5];
    const float* Wh1   = (const float*)d_in[6];
    const float* b1    = (const float*)d_in[7];
    const float* pW    = (const float*)d_in[8];
    const float* pb    = (const float*)d_in[9];
    const float* l0W   = (const float*)d_in[10];
    const float* l0b   = (const float*)d_in[11];
    const float* l1W   = (const float*)d_in[12];
    const float* l1b   = (const float*)d_in[13];
    const float* l2W   = (const float*)d_in[14];
    const float* l2b   = (const float*)d_in[15];
    const float* oW    = (const float*)d_in[16];
    const float* ob    = (const float*)d_in[17];

    // 32K + 32K staging + 3*8K weights + mbars = 90112 + 64 bytes
    const int smem_bytes = 90176;
    cudaFuncSetAttribute(lstm_persistent,
                         cudaFuncAttributeMaxDynamicSharedMemorySize, smem_bytes);

    init_kernel<<<(TT * BB + 255) / 256, 256>>>(x);
    lstm_persistent<<<NCTA, NT, smem_bytes>>>(Wh0, Wx0, b0, Wx1, Wh1, b1);
    final_kernel<<<BB, 256>>>(theta, pW, pb, l0W, l0b, l1W, l1b,
                              l2W, l2b, oW, ob, (float*)d_out);
}